// round 8
// baseline (speedup 1.0000x reference)
#include <cuda_runtime.h>
#include <cuda_bf16.h>

#define K_F 16
#define T_TYPES 4
#define OUT_W (K_F * T_TYPES)
#define PI_F 3.14159265358979323846f
#define BLK 256
#define NWARP (BLK / 32)
#define CHUNKS 4                       // 32-edge chunks per warp
#define EDGES_PER_BLK (BLK * CHUNKS)
#define TYPE_CAP (1 << 20)

// node -> matched one-hot type (-1 if none); filled by prep_kernel
__device__ signed char g_type[TYPE_CAP];

// Fused: zero the output AND build the per-node type table.
__global__ void prep_kernel(float4* __restrict__ out4, int n4,
                            const float* __restrict__ feat,
                            const float* __restrict__ ftu,
                            int V, int use_table)
{
    int i = blockIdx.x * blockDim.x + threadIdx.x;
    if (i < n4) out4[i] = make_float4(0.f, 0.f, 0.f, 0.f);
    if (use_table && i < V) {
        float fv = feat[i];
        signed char t = -1;
        #pragma unroll
        for (int j = 0; j < T_TYPES; j++)
            if (fv == ftu[j]) t = (signed char)j;
        g_type[i] = t;
    }
}

__global__ void __launch_bounds__(BLK, 6) edge_kernel(
    const float* __restrict__ feat,      // (V,1)  (fallback only)
    const float* __restrict__ dist,      // (E,1)
    const int*   __restrict__ src,       // (E,)
    const int*   __restrict__ dst,       // (E,)
    const float* __restrict__ cutoffs,   // (K,)
    const float* __restrict__ means,     // (K,)
    const float* __restrict__ scaling,   // (K,)
    const float* __restrict__ ftu,       // (T,)
    float*       __restrict__ out,       // (V, T*K)
    int E, int use_table)
{
    __shared__ float s_mean[K_F], s_nscal[K_F], s_cut[K_F], s_ftu[T_TYPES];
    __shared__ int s_unicos;
    // Per-warp staging regions: no block-wide barrier anywhere in the main
    // loop, so warps free-run and their compute (MUFU/FMA) and RED (LSU)
    // phases interleave on each SMSP instead of phase-locking.
    // Stride-5 float4 per edge: conflict-free for write (lane*5+g) and
    // transposed read ((q*4+i)*5+c) phases (R3-verified).
    __shared__ float4 s_val[NWARP][32 * 5];
    __shared__ int    s_code[NWARP][32];   // dst*4+type, or -1

    int tid  = threadIdx.x;
    int warp = tid >> 5;
    int lane = tid & 31;

    if (tid < K_F) {
        s_mean[tid]  = means[tid];
        s_nscal[tid] = -scaling[tid];
        s_cut[tid]   = cutoffs[tid];
    }
    if (tid < T_TYPES) s_ftu[tid] = ftu[tid];
    if (tid == 0) {
        int u = 1;
        #pragma unroll
        for (int k = 1; k < K_F; k++) u &= (cutoffs[k] == cutoffs[0]);
        s_unicos = u;
    }
    __syncthreads();   // only sync: params ready

    int unicos = s_unicos;
    int q = lane >> 2;
    int c = lane & 3;

    // Each warp owns CHUNKS consecutive 32-edge chunks.
    int warp_base = blockIdx.x * EDGES_PER_BLK + warp * (32 * CHUNKS);

    for (int ch = 0; ch < CHUNKS; ch++) {
        int e = warp_base + ch * 32 + lane;
        int code = -1;
        float d = 0.f;

        if (e < E) {
            d = dist[e];
            int s  = src[e];
            int dd = dst[e];
            int ty;
            if (use_table) {
                ty = g_type[s];
            } else {
                float fv = __ldg(&feat[s]);
                ty = -1;
                #pragma unroll
                for (int j = 0; j < T_TYPES; j++)
                    if (fv == s_ftu[j]) ty = j;
            }
            if (ty >= 0) code = dd * T_TYPES + ty;
        }

        if (code >= 0) {
            if (unicos) {
                float cu = s_cut[0];
                float cv = (d <= cu) ? 0.5f * (__cosf(PI_F * d / cu) + 1.0f) : 0.0f;
                #pragma unroll
                for (int g = 0; g < 4; g++) {
                    float dm0 = d - s_mean[4 * g + 0];
                    float dm1 = d - s_mean[4 * g + 1];
                    float dm2 = d - s_mean[4 * g + 2];
                    float dm3 = d - s_mean[4 * g + 3];
                    s_val[warp][lane * 5 + g] = make_float4(
                        cv * __expf(s_nscal[4 * g + 0] * dm0 * dm0),
                        cv * __expf(s_nscal[4 * g + 1] * dm1 * dm1),
                        cv * __expf(s_nscal[4 * g + 2] * dm2 * dm2),
                        cv * __expf(s_nscal[4 * g + 3] * dm3 * dm3));
                }
            } else {
                #pragma unroll
                for (int g = 0; g < 4; g++) {
                    float v[4];
                    #pragma unroll
                    for (int i = 0; i < 4; i++) {
                        int k = 4 * g + i;
                        float cu = s_cut[k];
                        float cv = (d <= cu) ? 0.5f * (__cosf(PI_F * d / cu) + 1.0f) : 0.0f;
                        float dm = d - s_mean[k];
                        v[i] = cv * __expf(s_nscal[k] * dm * dm);
                    }
                    s_val[warp][lane * 5 + g] = make_float4(v[0], v[1], v[2], v[3]);
                }
            }
        }
        s_code[warp][lane] = code;
        __syncwarp();

        // Transposed RED: quad covers one edge's contiguous 64B region.
        #pragma unroll
        for (int i = 0; i < 4; i++) {
            int el = q * 4 + i;
            int ec = s_code[warp][el];
            if (ec >= 0) {
                float4 val = s_val[warp][el * 5 + c];
                float* addr = out + ((size_t)ec << 4) + (c << 2);
                asm volatile(
                    "red.global.add.v4.f32 [%0], {%1, %2, %3, %4};"
                    :: "l"(addr), "f"(val.x), "f"(val.y), "f"(val.z), "f"(val.w)
                    : "memory");
            }
        }
        __syncwarp();   // staging reuse safety for next chunk
    }
}

extern "C" void kernel_launch(void* const* d_in, const int* in_sizes, int n_in,
                              void* d_out, int out_size)
{
    const float* feat    = (const float*)d_in[0];
    const float* dist    = (const float*)d_in[1];
    const int*   src     = (const int*)  d_in[2];
    const int*   dst     = (const int*)  d_in[3];
    const float* cutoffs = (const float*)d_in[4];
    const float* means   = (const float*)d_in[5];
    const float* scaling = (const float*)d_in[6];
    const float* ftu     = (const float*)d_in[7];
    float* out = (float*)d_out;

    int E = in_sizes[2];
    int V = in_sizes[0];
    int use_table = (V <= TYPE_CAP) ? 1 : 0;

    int n4 = out_size / 4;
    int prep_threads = (n4 > V) ? n4 : V;
    prep_kernel<<<(prep_threads + 255) / 256, 256>>>(
        (float4*)out, n4, feat, ftu, V, use_table);

    int blocks = (E + EDGES_PER_BLK - 1) / EDGES_PER_BLK;
    edge_kernel<<<blocks, BLK>>>(
        feat, dist, src, dst, cutoffs, means, scaling, ftu, out, E, use_table);
}

// round 10
// speedup vs baseline: 1.5483x; 1.5483x over previous
#include <cuda_runtime.h>
#include <cuda_bf16.h>

#define K_F 16
#define T_TYPES 4
#define OUT_W (K_F * T_TYPES)
#define PI_F 3.14159265358979323846f
#define BLK 256
#define EDGES_PER_BLK (BLK * 2)
#define TYPE_CAP (1 << 20)

// node -> matched one-hot type (-1 if none); filled by prep_kernel
__device__ signed char g_type[TYPE_CAP];

// Fused: zero the output AND build the per-node type table.
__global__ void prep_kernel(float4* __restrict__ out4, int n4,
                            const float* __restrict__ feat,
                            const float* __restrict__ ftu,
                            int V, int use_table)
{
    int i = blockIdx.x * blockDim.x + threadIdx.x;
    if (i < n4) out4[i] = make_float4(0.f, 0.f, 0.f, 0.f);
    if (use_table && i < V) {
        float fv = feat[i];
        signed char t = -1;
        #pragma unroll
        for (int j = 0; j < T_TYPES; j++)
            if (fv == ftu[j]) t = (signed char)j;
        g_type[i] = t;
    }
}

__global__ void __launch_bounds__(BLK) edge_kernel(
    const float* __restrict__ feat,      // (V,1)  (fallback only)
    const float* __restrict__ dist,      // (E,1)
    const int*   __restrict__ src,       // (E,)
    const int*   __restrict__ dst,       // (E,)
    const float* __restrict__ cutoffs,   // (K,)
    const float* __restrict__ means,     // (K,)
    const float* __restrict__ scaling,   // (K,)
    const float* __restrict__ ftu,       // (T,)
    float*       __restrict__ out,       // (V, T*K)
    int E, int use_table)
{
    __shared__ float s_mean[K_F], s_nscal[K_F], s_cut[K_F], s_ftu[T_TYPES];
    __shared__ int s_unicos;
    // Stride-5 float4 per edge: conflict-free for write (tid*5+g) and
    // transposed read ((q*4+i)*5+c) phases (R3/R4-verified). Reused across
    // the two 256-edge phases -> same 21KB footprint as R4.
    __shared__ float4 s_val[BLK * 5];
    __shared__ int    s_code[BLK];        // dst*4+type, or -1

    int tid = threadIdx.x;
    if (tid < K_F) {
        s_mean[tid]  = means[tid];
        s_nscal[tid] = -scaling[tid];
        s_cut[tid]   = cutoffs[tid];
    }
    if (tid < T_TYPES) s_ftu[tid] = ftu[tid];
    if (tid == 0) {
        int u = 1;
        #pragma unroll
        for (int k = 1; k < K_F; k++) u &= (cutoffs[k] == cutoffs[0]);
        s_unicos = u;
    }
    __syncthreads();

    int base = blockIdx.x * EDGES_PER_BLK;
    int e0 = base + tid;
    int e1 = base + BLK + tid;
    bool ok0 = (e0 < E), ok1 = (e1 < E);

    // Front-batch ALL global loads + both gathers (max MLP).
    float d0 = 0.f, d1 = 0.f;
    int s0 = 0, s1 = 0, dd0 = 0, dd1 = 0;
    if (ok0) { d0 = dist[e0]; s0 = src[e0]; dd0 = dst[e0]; }
    if (ok1) { d1 = dist[e1]; s1 = src[e1]; dd1 = dst[e1]; }

    int ty0 = -1, ty1 = -1;
    if (use_table) {
        if (ok0) ty0 = g_type[s0];
        if (ok1) ty1 = g_type[s1];
    } else {
        float fv0 = ok0 ? __ldg(&feat[s0]) : -1.f;
        float fv1 = ok1 ? __ldg(&feat[s1]) : -1.f;
        #pragma unroll
        for (int j = 0; j < T_TYPES; j++) {
            if (ok0 && fv0 == s_ftu[j]) ty0 = j;
            if (ok1 && fv1 == s_ftu[j]) ty1 = j;
        }
    }

    int unicos = s_unicos;
    int q = tid >> 2;
    int c = tid & 3;

    #pragma unroll
    for (int pass = 0; pass < 2; pass++) {
        float d    = pass ? d1 : d0;
        int   ty   = pass ? ty1 : ty0;
        int   dd   = pass ? dd1 : dd0;
        int   code = (ty >= 0) ? (dd * T_TYPES + ty) : -1;

        // Compute UNCONDITIONALLY: v[k] depends only on d, so it proceeds
        // while the g_type gather is still in flight (code gates only the
        // tiny s_code store and the REDs).
        if (unicos) {
            float cu = s_cut[0];
            float cv = (d <= cu) ? 0.5f * (__cosf(PI_F * d / cu) + 1.0f) : 0.0f;
            #pragma unroll
            for (int g = 0; g < 4; g++) {
                float dm0 = d - s_mean[4 * g + 0];
                float dm1 = d - s_mean[4 * g + 1];
                float dm2 = d - s_mean[4 * g + 2];
                float dm3 = d - s_mean[4 * g + 3];
                s_val[tid * 5 + g] = make_float4(
                    cv * __expf(s_nscal[4 * g + 0] * dm0 * dm0),
                    cv * __expf(s_nscal[4 * g + 1] * dm1 * dm1),
                    cv * __expf(s_nscal[4 * g + 2] * dm2 * dm2),
                    cv * __expf(s_nscal[4 * g + 3] * dm3 * dm3));
            }
        } else {
            #pragma unroll
            for (int g = 0; g < 4; g++) {
                float v[4];
                #pragma unroll
                for (int i = 0; i < 4; i++) {
                    int k = 4 * g + i;
                    float cu = s_cut[k];
                    float cv = (d <= cu) ? 0.5f * (__cosf(PI_F * d / cu) + 1.0f) : 0.0f;
                    float dm = d - s_mean[k];
                    v[i] = cv * __expf(s_nscal[k] * dm * dm);
                }
                s_val[tid * 5 + g] = make_float4(v[0], v[1], v[2], v[3]);
            }
        }
        s_code[tid] = code;
        __syncthreads();

        // Transposed RED: quad q handles edges q*4..q*4+3; per step the
        // quad's 4 red.v4 cover one edge's contiguous 64B-aligned region.
        #pragma unroll
        for (int i = 0; i < 4; i++) {
            int el = q * 4 + i;
            int ec = s_code[el];
            if (ec >= 0) {
                float4 val = s_val[el * 5 + c];
                float* addr = out + ((size_t)ec << 4) + (c << 2);
                asm volatile(
                    "red.global.add.v4.f32 [%0], {%1, %2, %3, %4};"
                    :: "l"(addr), "f"(val.x), "f"(val.y), "f"(val.z), "f"(val.w)
                    : "memory");
            }
        }
        __syncthreads();   // staging buffer reuse safety for pass 1
    }
}

extern "C" void kernel_launch(void* const* d_in, const int* in_sizes, int n_in,
                              void* d_out, int out_size)
{
    const float* feat    = (const float*)d_in[0];
    const float* dist    = (const float*)d_in[1];
    const int*   src     = (const int*)  d_in[2];
    const int*   dst     = (const int*)  d_in[3];
    const float* cutoffs = (const float*)d_in[4];
    const float* means   = (const float*)d_in[5];
    const float* scaling = (const float*)d_in[6];
    const float* ftu     = (const float*)d_in[7];
    float* out = (float*)d_out;

    int E = in_sizes[2];
    int V = in_sizes[0];
    int use_table = (V <= TYPE_CAP) ? 1 : 0;

    int n4 = out_size / 4;
    int prep_threads = (n4 > V) ? n4 : V;
    prep_kernel<<<(prep_threads + 255) / 256, 256>>>(
        (float4*)out, n4, feat, ftu, V, use_table);

    int blocks = (E + EDGES_PER_BLK - 1) / EDGES_PER_BLK;
    edge_kernel<<<blocks, BLK>>>(
        feat, dist, src, dst, cutoffs, means, scaling, ftu, out, E, use_table);
}

// round 12
// speedup vs baseline: 1.8122x; 1.1705x over previous
#include <cuda_runtime.h>
#include <cuda_bf16.h>

#define K_F 16
#define T_TYPES 4
#define OUT_W (K_F * T_TYPES)
#define PI_F 3.14159265358979323846f
#define BLK 256
#define EDGES_PER_WARP 64
#define EDGES_PER_BLK (BLK / 32 * EDGES_PER_WARP)   // 512
#define TYPE_CAP (1 << 20)

// node -> matched one-hot type (-1 if none); filled by prep_kernel
__device__ signed char g_type[TYPE_CAP];

// Fused: zero the output AND build the per-node type table.
__global__ void prep_kernel(float4* __restrict__ out4, int n4,
                            const float* __restrict__ feat,
                            const float* __restrict__ ftu,
                            int V, int use_table)
{
    int i = blockIdx.x * blockDim.x + threadIdx.x;
    if (i < n4) out4[i] = make_float4(0.f, 0.f, 0.f, 0.f);
    if (use_table && i < V) {
        float fv = feat[i];
        signed char t = -1;
        #pragma unroll
        for (int j = 0; j < T_TYPES; j++)
            if (fv == ftu[j]) t = (signed char)j;
        g_type[i] = t;
    }
}

// Quad-cooperative: lane l (chunk c = l&3) computes values [4c..4c+3] for the
// 4 edges of its quad and REDs them directly. Only d and code cross lanes
// (one shfl each per step) -> the entire smem transpose is eliminated.
__global__ void __launch_bounds__(BLK) edge_kernel(
    const float* __restrict__ feat,      // (V,1)  (fallback only)
    const float* __restrict__ dist,      // (E,1)
    const int*   __restrict__ src,       // (E,)
    const int*   __restrict__ dst,       // (E,)
    const float* __restrict__ cutoffs,   // (K,)
    const float* __restrict__ means,     // (K,)
    const float* __restrict__ scaling,   // (K,)
    const float* __restrict__ ftu,       // (T,)
    float*       __restrict__ out,       // (V, T*K)
    int E, int use_table)
{
    __shared__ float s_ftu[T_TYPES];
    __shared__ int s_unicos;

    int tid  = threadIdx.x;
    int warp = tid >> 5;
    int lane = tid & 31;
    int c    = lane & 3;

    if (tid < T_TYPES) s_ftu[tid] = ftu[tid];
    if (tid == 0) {
        int u = 1;
        #pragma unroll
        for (int k = 1; k < K_F; k++) u &= (cutoffs[k] == cutoffs[0]);
        s_unicos = u;
    }

    // Per-lane radial params for this lane's 4 k's -> registers, no LDS in
    // the hot loop. (4 distinct addresses per warp; L1-resident.)
    float m[4], ns[4], cu4[4], picu[4];
    #pragma unroll
    for (int k = 0; k < 4; k++) {
        m[k]    = __ldg(&means[4 * c + k]);
        ns[k]   = -__ldg(&scaling[4 * c + k]);
        cu4[k]  = __ldg(&cutoffs[4 * c + k]);
        picu[k] = PI_F / cu4[k];
    }
    float cu0   = __ldg(&cutoffs[0]);
    float picu0 = PI_F / cu0;

    __syncthreads();
    int unicos = s_unicos;

    // Warp-contiguous edges: warp covers 64, front-batch both edges' loads.
    int wbase = blockIdx.x * EDGES_PER_BLK + warp * EDGES_PER_WARP;
    int e0 = wbase + lane;
    int e1 = wbase + 32 + lane;
    bool ok0 = (e0 < E), ok1 = (e1 < E);

    float d0 = 0.f, d1 = 0.f;
    int s0 = 0, s1 = 0, dd0 = 0, dd1 = 0;
    if (ok0) { d0 = dist[e0]; s0 = src[e0]; dd0 = dst[e0]; }
    if (ok1) { d1 = dist[e1]; s1 = src[e1]; dd1 = dst[e1]; }

    int ty0 = -1, ty1 = -1;
    if (use_table) {
        if (ok0) ty0 = g_type[s0];
        if (ok1) ty1 = g_type[s1];
    } else {
        float fv0 = ok0 ? __ldg(&feat[s0]) : -1.f;
        float fv1 = ok1 ? __ldg(&feat[s1]) : -1.f;
        #pragma unroll
        for (int j = 0; j < T_TYPES; j++) {
            if (ok0 && fv0 == s_ftu[j]) ty0 = j;
            if (ok1 && fv1 == s_ftu[j]) ty1 = j;
        }
    }
    int code0 = (ty0 >= 0) ? (dd0 * T_TYPES + ty0) : -1;
    int code1 = (ty1 >= 0) ? (dd1 * T_TYPES + ty1) : -1;

    int qbase = lane & ~3;   // quad leader lane

    #pragma unroll
    for (int pass = 0; pass < 2; pass++) {
        float dp  = pass ? d1 : d0;
        int   cp  = pass ? code1 : code0;

        #pragma unroll
        for (int i = 0; i < 4; i++) {
            int srcl = qbase | i;
            float di = __shfl_sync(0xffffffffu, dp, srcl);
            int   ci = __shfl_sync(0xffffffffu, cp, srcl);

            float v0, v1, v2, v3;
            if (unicos) {
                float cv = (di <= cu0)
                         ? 0.5f * (__cosf(picu0 * di) + 1.0f) : 0.0f;
                float dm0 = di - m[0], dm1 = di - m[1];
                float dm2 = di - m[2], dm3 = di - m[3];
                v0 = cv * __expf(ns[0] * dm0 * dm0);
                v1 = cv * __expf(ns[1] * dm1 * dm1);
                v2 = cv * __expf(ns[2] * dm2 * dm2);
                v3 = cv * __expf(ns[3] * dm3 * dm3);
            } else {
                float v[4];
                #pragma unroll
                for (int k = 0; k < 4; k++) {
                    float cv = (di <= cu4[k])
                             ? 0.5f * (__cosf(picu[k] * di) + 1.0f) : 0.0f;
                    float dm = di - m[k];
                    v[k] = cv * __expf(ns[k] * dm * dm);
                }
                v0 = v[0]; v1 = v[1]; v2 = v[2]; v3 = v[3];
            }

            if (ci >= 0) {
                // Quad's 4 lanes cover one contiguous 64B-aligned region.
                float* addr = out + ((size_t)ci << 4) + (c << 2);
                asm volatile(
                    "red.global.add.v4.f32 [%0], {%1, %2, %3, %4};"
                    :: "l"(addr), "f"(v0), "f"(v1), "f"(v2), "f"(v3)
                    : "memory");
            }
        }
    }
}

extern "C" void kernel_launch(void* const* d_in, const int* in_sizes, int n_in,
                              void* d_out, int out_size)
{
    const float* feat    = (const float*)d_in[0];
    const float* dist    = (const float*)d_in[1];
    const int*   src     = (const int*)  d_in[2];
    const int*   dst     = (const int*)  d_in[3];
    const float* cutoffs = (const float*)d_in[4];
    const float* means   = (const float*)d_in[5];
    const float* scaling = (const float*)d_in[6];
    const float* ftu     = (const float*)d_in[7];
    float* out = (float*)d_out;

    int E = in_sizes[2];
    int V = in_sizes[0];
    int use_table = (V <= TYPE_CAP) ? 1 : 0;

    int n4 = out_size / 4;
    int prep_threads = (n4 > V) ? n4 : V;
    prep_kernel<<<(prep_threads + 255) / 256, 256>>>(
        (float4*)out, n4, feat, ftu, V, use_table);

    int blocks = (E + EDGES_PER_BLK - 1) / EDGES_PER_BLK;
    edge_kernel<<<blocks, BLK>>>(
        feat, dist, src, dst, cutoffs, means, scaling, ftu, out, E, use_table);
}